// round 6
// baseline (speedup 1.0000x reference)
#include <cuda_runtime.h>
#include <cuda_fp16.h>

#define PNUM   512
#define BATCH  256
#define LPREDS 2
#define NLB    (LPREDS * BATCH)
#define NBLK   (2 * NLB)      // 1024 blocks
#define NGRP   32

__device__ float    g_part[NBLK];   // per-block results (plain stores)
__device__ unsigned g_cnt[NGRP];    // zero-init; self-reset by group folder
__device__ float    g_sum;          // zero-init; self-reset by final block
__device__ unsigned g_done;         // zero-init; self-reset by final block

// smoothL1 on both components at once: d=p-q; u=min(|d|,1); acc += u*(|d|-0.5u)
__device__ __forceinline__ void sl1_h2(const unsigned pu, const unsigned qu,
                                       const __half2 one2, const __half2 nh2,
                                       __half2& acc) {
    __half2 p = *reinterpret_cast<const __half2*>(&pu);
    __half2 q = *reinterpret_cast<const __half2*>(&qu);
    __half2 d = __hsub2(p, q);
    __half2 a = __habs2(d);
    __half2 u = __hmin2(a, one2);
    __half2 w = __hfma2(u, nh2, a);      // |d| - 0.5u
    acc       = __hfma2(u, w, acc);      // += u*(|d| - 0.5u)
}

__global__ __launch_bounds__(128, 7)
void poly_main(const float* __restrict__ pred, const float* __restrict__ gt,
               float* __restrict__ out) {
    // point-packed fp16: one half2 per point (x,y)
    __shared__ __align__(16) __half2 sg[2 * PNUM];     // gt doubled (cyclic)
    __shared__ __align__(16) __half2 sp[4][PNUM];      // pred rotated by s=0..3
    __shared__ float wm[4];

    const int t   = threadIdx.x;
    const int bid = blockIdx.x;
    const int lb  = bid & (NLB - 1);
    const int h   = bid >> 9;              // which half of the 512 shifts
    const int b   = lb & (BATCH - 1);

    const float2* pv = (const float2*)(pred + (size_t)lb * PNUM * 2);
    const float2* gv = (const float2*)(gt   + (size_t)b  * PNUM * 2);

    #pragma unroll
    for (int k = t; k < PNUM; k += 128) {
        __half2 gh = __float22half2_rn(gv[k]);
        sg[k]        = gh;
        sg[k + PNUM] = gh;
        __half2 ph = __float22half2_rn(pv[k]);
        sp[0][k]               = ph;   // sp[s][j] = p[(j+s) % 512]
        sp[1][(k + 511) & 511] = ph;
        sp[2][(k + 510) & 511] = ph;
        sp[3][(k + 509) & 511] = ph;
    }
    __syncthreads();

    const int warp = t >> 5;
    const int lane = t & 31;
    const int r    = warp;                 // shift residue mod 4 handled by this warp
    const int s    = (4 - r) & 3;          // pred rotation so q base is 4-point aligned
    const int A    = h * 256 + r + 8 * lane;   // shift A; shift B = A + 4

    const uint4* qf = reinterpret_cast<const uint4*>(sg) + ((A + s) >> 2);
    const uint4* pf = reinterpret_cast<const uint4*>(sp[s]);

    const __half2 one2 = __floats2half2_rn(1.0f, 1.0f);
    const __half2 nh2  = __floats2half2_rn(-0.5f, -0.5f);
    const __half2 z2   = __floats2half2_rn(0.0f, 0.0f);

    __half2 hA0=z2,hA1=z2,hA2=z2,hA3=z2, hB0=z2,hB1=z2,hB2=z2,hB3=z2;
    float fAx=0.f, fAy=0.f, fBx=0.f, fBy=0.f;

    uint4 Pprev = pf[127];                 // cyclic wrap: B's m=0 terms use j=508..511

    for (int c = 0; c < 16; ++c) {
        #pragma unroll
        for (int mm = 0; mm < 8; ++mm) {
            const int m = c * 8 + mm;
            uint4 P = pf[m];
            uint4 Q = qf[m];
            // shift A: pairs (p[4m+e], g[A+4m+e])
            sl1_h2(P.x, Q.x, one2, nh2, hA0);
            sl1_h2(P.y, Q.y, one2, nh2, hA1);
            sl1_h2(P.z, Q.z, one2, nh2, hA2);
            sl1_h2(P.w, Q.w, one2, nh2, hA3);
            // shift B = A+4: same Q, pred delayed one float4
            sl1_h2(Pprev.x, Q.x, one2, nh2, hB0);
            sl1_h2(Pprev.y, Q.y, one2, nh2, hB1);
            sl1_h2(Pprev.z, Q.z, one2, nh2, hB2);
            sl1_h2(Pprev.w, Q.w, one2, nh2, hB3);
            Pprev = P;
        }
        // drain fp16 chunk accumulators into fp32 (keeps fp16 magnitudes small)
        __half2 cA = __hadd2(__hadd2(hA0, hA1), __hadd2(hA2, hA3));
        __half2 cB = __hadd2(__hadd2(hB0, hB1), __hadd2(hB2, hB3));
        fAx += __low2float(cA);  fAy += __high2float(cA);
        fBx += __low2float(cB);  fBy += __high2float(cB);
        hA0=z2;hA1=z2;hA2=z2;hA3=z2; hB0=z2;hB1=z2;hB2=z2;hB3=z2;
    }

    float v = fminf(fAx + fAy, fBx + fBy);   // min over this thread's two shifts

    #pragma unroll
    for (int o = 16; o; o >>= 1)
        v = fminf(v, __shfl_xor_sync(0xffffffffu, v, o));
    if (lane == 0) wm[warp] = v;
    __syncthreads();

    if (t == 0) {
        float bv = fminf(fminf(wm[0], wm[1]), fminf(wm[2], wm[3]));
        g_part[bid] = bv;
        __threadfence();
        const int grp = bid & (NGRP - 1);   // bid and bid+512 share a group
        unsigned old = atomicAdd(&g_cnt[grp], 1u);
        if (old == 31u) {
            // last of this group's 32 blocks: fold its 16 lb-pairs
            g_cnt[grp] = 0u;                 // self-reset (kernel boundary orders vs next replay)
            const volatile float* gp = g_part;
            float acc = 0.0f;
            #pragma unroll
            for (int k = 0; k < 16; ++k) {
                int i = grp + 32 * k;
                acc += fminf(gp[i], gp[i + NLB]);
            }
            atomicAdd(&g_sum, acc);
            __threadfence();
            unsigned dn = atomicAdd(&g_done, 1u);
            if (dn == NGRP - 1) {            // last group: all g_sum adds visible
                float ssum = *((volatile float*)&g_sum);
                *out = ssum * (1.0f / ((float)PNUM * BATCH * LPREDS));
                g_sum  = 0.0f;               // self-reset for next replay
                g_done = 0u;
            }
        }
    }
}

extern "C" void kernel_launch(void* const* d_in, const int* in_sizes, int n_in,
                              void* d_out, int out_size) {
    const float* pred = (const float*)d_in[0];   // (L, B, P, 2) fp32
    const float* gt   = (const float*)d_in[1];   // (B, P, 2) fp32
    float* out = (float*)d_out;

    poly_main<<<NBLK, 128>>>(pred, gt, out);
}

// round 7
// speedup vs baseline: 1.0656x; 1.0656x over previous
#include <cuda_runtime.h>
#include <cuda_fp16.h>

#define PNUM   512
#define BATCH  256
#define LPREDS 2
#define NLB    (LPREDS * BATCH)
#define NBLK   (2 * NLB)      // 1024 blocks

__device__ float g_part[NBLK];   // per-block partial mins (every slot written every run)

// smoothL1 on both components at once: d=p-q; u=min(|d|,1); acc += u*(|d|-0.5u)
__device__ __forceinline__ void sl1_h2(const unsigned pu, const unsigned qu,
                                       const __half2 one2, const __half2 nh2,
                                       __half2& acc) {
    __half2 p = *reinterpret_cast<const __half2*>(&pu);
    __half2 q = *reinterpret_cast<const __half2*>(&qu);
    __half2 d = __hsub2(p, q);
    __half2 a = __habs2(d);
    __half2 u = __hmin2(a, one2);
    __half2 w = __hfma2(u, nh2, a);      // |d| - 0.5u
    acc       = __hfma2(u, w, acc);      // += u*(|d| - 0.5u)
}

__global__ __launch_bounds__(128, 7)
void poly_main(const float* __restrict__ pred, const float* __restrict__ gt) {
    // point-packed fp16: one half2 per point (x,y)
    __shared__ __align__(16) __half2 sg[2 * PNUM];     // gt doubled (cyclic)
    __shared__ __align__(16) __half2 sp[4][PNUM];      // pred rotated by s=0..3
    __shared__ float wm[4];

    const int t   = threadIdx.x;
    const int bid = blockIdx.x;
    const int lb  = bid & (NLB - 1);
    const int h   = bid >> 9;              // which half of the 512 shifts
    const int b   = lb & (BATCH - 1);

    const float2* pv = (const float2*)(pred + (size_t)lb * PNUM * 2);
    const float2* gv = (const float2*)(gt   + (size_t)b  * PNUM * 2);

    #pragma unroll
    for (int k = t; k < PNUM; k += 128) {
        __half2 gh = __float22half2_rn(gv[k]);
        sg[k]        = gh;
        sg[k + PNUM] = gh;
        __half2 ph = __float22half2_rn(pv[k]);
        sp[0][k]               = ph;   // sp[s][j] = p[(j+s) % 512]
        sp[1][(k + 511) & 511] = ph;
        sp[2][(k + 510) & 511] = ph;
        sp[3][(k + 509) & 511] = ph;
    }
    __syncthreads();

    const int warp = t >> 5;
    const int lane = t & 31;
    const int r    = warp;                 // shift residue mod 4 handled by this warp
    const int s    = (4 - r) & 3;          // pred rotation so q base is 4-point aligned
    const int A    = h * 256 + r + 8 * lane;   // shift A; shift B = A + 4

    const uint4* qf = reinterpret_cast<const uint4*>(sg) + ((A + s) >> 2);
    const uint4* pf = reinterpret_cast<const uint4*>(sp[s]);

    const __half2 one2 = __floats2half2_rn(1.0f, 1.0f);
    const __half2 nh2  = __floats2half2_rn(-0.5f, -0.5f);
    const __half2 z2   = __floats2half2_rn(0.0f, 0.0f);

    __half2 hA0=z2,hA1=z2,hA2=z2,hA3=z2, hB0=z2,hB1=z2,hB2=z2,hB3=z2;
    float fAx=0.f, fAy=0.f, fBx=0.f, fBy=0.f;

    uint4 Pprev = pf[127];                 // cyclic wrap: B's m=0 terms use j=508..511

    for (int c = 0; c < 8; ++c) {          // 16 m-iters per fp16 chunk
        #pragma unroll
        for (int mm = 0; mm < 16; ++mm) {
            const int m = c * 16 + mm;
            uint4 P = pf[m];
            uint4 Q = qf[m];
            // shift A: pairs (p[4m+e], g[A+4m+e])
            sl1_h2(P.x, Q.x, one2, nh2, hA0);
            sl1_h2(P.y, Q.y, one2, nh2, hA1);
            sl1_h2(P.z, Q.z, one2, nh2, hA2);
            sl1_h2(P.w, Q.w, one2, nh2, hA3);
            // shift B = A+4: same Q, pred delayed one float4
            sl1_h2(Pprev.x, Q.x, one2, nh2, hB0);
            sl1_h2(Pprev.y, Q.y, one2, nh2, hB1);
            sl1_h2(Pprev.z, Q.z, one2, nh2, hB2);
            sl1_h2(Pprev.w, Q.w, one2, nh2, hB3);
            Pprev = P;
        }
        // drain fp16 chunk accumulators into fp32 (keeps fp16 magnitudes small)
        __half2 cA = __hadd2(__hadd2(hA0, hA1), __hadd2(hA2, hA3));
        __half2 cB = __hadd2(__hadd2(hB0, hB1), __hadd2(hB2, hB3));
        fAx += __low2float(cA);  fAy += __high2float(cA);
        fBx += __low2float(cB);  fBy += __high2float(cB);
        hA0=z2;hA1=z2;hA2=z2;hA3=z2; hB0=z2;hB1=z2;hB2=z2;hB3=z2;
    }

    float v = fminf(fAx + fAy, fBx + fBy);   // min over this thread's two shifts

    #pragma unroll
    for (int o = 16; o; o >>= 1)
        v = fminf(v, __shfl_xor_sync(0xffffffffu, v, o));
    if (lane == 0) wm[warp] = v;
    __syncthreads();
    if (t == 0)
        g_part[bid] = fminf(fminf(wm[0], wm[1]), fminf(wm[2], wm[3]));
}

__global__ void finish_kernel(float* __restrict__ out) {
    __shared__ float wm[16];
    const int t = threadIdx.x;   // 512 threads: one per lb

    cudaGridDependencySynchronize();   // PDL: wait for poly_main completion + visibility

    float v = fminf(g_part[t], g_part[t + NLB]);   // min over the two halves
    #pragma unroll
    for (int o = 16; o; o >>= 1)
        v += __shfl_xor_sync(0xffffffffu, v, o);
    if ((t & 31) == 0) wm[t >> 5] = v;
    __syncthreads();
    if (t < 16) {
        v = wm[t];
        #pragma unroll
        for (int o = 8; o; o >>= 1)
            v += __shfl_xor_sync(0x0000ffffu, v, o);
        if (t == 0)
            *out = v * (1.0f / ((float)PNUM * BATCH * LPREDS));
    }
}

extern "C" void kernel_launch(void* const* d_in, const int* in_sizes, int n_in,
                              void* d_out, int out_size) {
    const float* pred = (const float*)d_in[0];   // (L, B, P, 2) fp32
    const float* gt   = (const float*)d_in[1];   // (B, P, 2) fp32
    float* out = (float*)d_out;

    poly_main<<<NBLK, 128>>>(pred, gt);

    // Finish kernel with programmatic dependent launch: launches while poly_main
    // drains; cudaGridDependencySynchronize() inside gates the actual reads.
    cudaLaunchConfig_t cfg = {};
    cfg.gridDim  = dim3(1, 1, 1);
    cfg.blockDim = dim3(NLB, 1, 1);
    cfg.dynamicSmemBytes = 0;
    cfg.stream = 0;
    cudaLaunchAttribute attr[1];
    attr[0].id = cudaLaunchAttributeProgrammaticStreamSerialization;
    attr[0].val.programmaticStreamSerializationAllowed = 1;
    cfg.attrs = attr;
    cfg.numAttrs = 1;
    cudaLaunchKernelEx(&cfg, finish_kernel, out);
}